// round 2
// baseline (speedup 1.0000x reference)
#include <cuda_runtime.h>
#include <math.h>

// SimpleGaussianSplatting: B=4096 rays, N=100000 pts, top-K=10 nearest, weighted blend.
// R2: (a) 1152 warp-tasks (128 ray-groups x 9 point-slices) + global-scratch merge
//     -> all 148 SMs busy while keeping per-warp streams long (L=11136) so the
//     warp-any insertion guard stays ~13% triggered.
//     (b) packed fp32x2 scoring (fma.rn.f32x2): 3 packed FMA score 2 points.

#define N_PTS    100000
#define SLICES   9
#define L_PTS    11136                 // points per warp-slice, multiple of 64
#define N_PAD    (SLICES * L_PTS)      // 100224
#define N_RAYS   4096
#define K_TOP    10
#define N_GROUPS (N_RAYS / 32)         // 128
#define N_TASKS  (N_GROUPS * SLICES)   // 1152
#define N_BLK    (N_TASKS / 8)         // 144 blocks x 8 warps

#define F_INF __int_as_float(0x7f800000)

// Packed pair layout: g_pk[i] = (x0,x1,y0,y1), g_pk2[i] = (z0,z1,|p0|^2,|p1|^2)
__device__ float4 g_pk [N_PAD / 2];
__device__ float4 g_pk2[N_PAD / 2];
__device__ float4 g_rays[N_RAYS];      // (-2cx, -2cy, -2cz, |c|^2)
__device__ float  g_ps[N_TASKS * K_TOP * 32];
__device__ int    g_pi[N_TASKS * K_TOP * 32];

#define FMA2(d, a, b, c) \
    asm("fma.rn.f32x2 %0, %1, %2, %3;" : "=l"(d) : "l"(a), "l"(b), "l"(c))
#define PACK2(d, f) \
    asm("mov.b64 %0, {%1, %1};" : "=l"(d) : "r"(__float_as_int(f)))
#define UNPK2(lo, hi, d) \
    asm("mov.b64 {%0, %1}, %2;" : "=f"(lo), "=f"(hi) : "l"(d))

__global__ void prep_pairs_kernel(const float* __restrict__ xyz) {
    int i = blockIdx.x * blockDim.x + threadIdx.x;
    if (i >= N_PAD / 2) return;
    int p0 = 2 * i, p1 = 2 * i + 1;
    float x0 = 0.f, y0 = 0.f, z0 = 0.f, w0 = F_INF;
    float x1 = 0.f, y1 = 0.f, z1 = 0.f, w1 = F_INF;
    if (p0 < N_PTS) {
        x0 = xyz[3 * p0 + 0]; y0 = xyz[3 * p0 + 1]; z0 = xyz[3 * p0 + 2];
        w0 = x0 * x0 + y0 * y0 + z0 * z0;
    }
    if (p1 < N_PTS) {
        x1 = xyz[3 * p1 + 0]; y1 = xyz[3 * p1 + 1]; z1 = xyz[3 * p1 + 2];
        w1 = x1 * x1 + y1 * y1 + z1 * z1;
    }
    g_pk [i] = make_float4(x0, x1, y0, y1);
    g_pk2[i] = make_float4(z0, z1, w0, w1);
}

__global__ void prep_rays_kernel(const float* __restrict__ ro,
                                 const float* __restrict__ rd) {
    int i = blockIdx.x * blockDim.x + threadIdx.x;
    if (i >= N_RAYS) return;
    float cx = ro[3 * i + 0] + 3.f * rd[3 * i + 0];
    float cy = ro[3 * i + 1] + 3.f * rd[3 * i + 1];
    float cz = ro[3 * i + 2] + 3.f * rd[3 * i + 2];
    g_rays[i] = make_float4(-2.f * cx, -2.f * cy, -2.f * cz,
                            cx * cx + cy * cy + cz * cz);
}

__device__ __forceinline__ float sigmoidf_(float x) {
    return 1.f / (1.f + expf(-x));
}

// Branchless sorted insert (ascending); fully unrolled -> stays in registers.
__device__ __forceinline__ void topk_insert(float (&sa)[K_TOP], int (&ia)[K_TOP],
                                            float s, int vi) {
    bool cc[K_TOP];
#pragma unroll
    for (int j = 0; j < K_TOP; ++j) cc[j] = s < sa[j];
#pragma unroll
    for (int j = K_TOP - 1; j >= 1; --j) {
        sa[j] = cc[j - 1] ? sa[j - 1] : (cc[j] ? s  : sa[j]);
        ia[j] = cc[j - 1] ? ia[j - 1] : (cc[j] ? vi : ia[j]);
    }
    sa[0] = cc[0] ? s  : sa[0];
    ia[0] = cc[0] ? vi : ia[0];
}

__global__ __launch_bounds__(256, 1)
void scan_kernel() {
    __shared__ ulonglong2 sA[8][32];   // (x0x1, y0y1) bit-packed
    __shared__ ulonglong2 sB[8][32];   // (z0z1, w0w1)

    const int lane = threadIdx.x & 31;
    const int w    = threadIdx.x >> 5;
    const int task  = blockIdx.x * 8 + w;         // 0..1151
    const int group = task / SLICES;              // 0..127
    const int slice = task - group * SLICES;      // 0..8
    const int ray   = group * 32 + lane;

    const float4 rc = g_rays[ray];
    unsigned long long rcx2, rcy2, rcz2;
    PACK2(rcx2, rc.x);
    PACK2(rcy2, rc.y);
    PACK2(rcz2, rc.z);

    float sa[K_TOP];
    int   ia[K_TOP];
#pragma unroll
    for (int j = 0; j < K_TOP; ++j) { sa[j] = F_INF; ia[j] = 0; }

    const ulonglong2* __restrict__ gA = reinterpret_cast<const ulonglong2*>(g_pk);
    const ulonglong2* __restrict__ gB = reinterpret_cast<const ulonglong2*>(g_pk2);
    const int pbase = slice * (L_PTS / 2);        // pair index base (5568/slice)

    ulonglong2 nA = gA[pbase + lane];             // prefetch chunk 0
    ulonglong2 nB = gB[pbase + lane];

    for (int c = 0; c < L_PTS / 2; c += 32) {
        __syncwarp();
        sA[w][lane] = nA;
        sB[w][lane] = nB;
        __syncwarp();
        if (c + 32 < L_PTS / 2) {
            nA = gA[pbase + c + 32 + lane];       // hide L2 latency
            nB = gB[pbase + c + 32 + lane];
        }

#pragma unroll 4
        for (int k = 0; k < 32; ++k) {
            ulonglong2 A = sA[w][k];              // broadcast LDS.128
            ulonglong2 B = sB[w][k];
            unsigned long long t;
            FMA2(t, rcz2, B.x, B.y);              // z*rcz + |p|^2   (2 pts)
            FMA2(t, rcy2, A.y, t);                // + y*rcy
            FMA2(t, rcx2, A.x, t);                // + x*rcx
            float s0, s1;
            UNPK2(s0, s1, t);                     // free: register-pair split
            const int pi = (pbase + c + k) * 2;
            // per-point warp-uniform guards (per-pair guard doubles body rate)
            if (__any_sync(0xffffffffu, s0 < sa[K_TOP - 1]))
                topk_insert(sa, ia, s0, pi);
            if (__any_sync(0xffffffffu, s1 < sa[K_TOP - 1]))
                topk_insert(sa, ia, s1, pi + 1);
        }
    }

    // publish sorted per-task candidates, coalesced by lane
#pragma unroll
    for (int j = 0; j < K_TOP; ++j) {
        g_ps[(task * K_TOP + j) * 32 + lane] = sa[j];
        g_pi[(task * K_TOP + j) * 32 + lane] = ia[j];
    }
}

__global__ void merge_kernel(const float* __restrict__ fdc,
                             const float* __restrict__ opac,
                             float* __restrict__ out) {
    const int r = blockIdx.x * blockDim.x + threadIdx.x;   // one thread per ray
    if (r >= N_RAYS) return;
    const int group = r >> 5;
    const int lane  = r & 31;

    float ms[K_TOP];
    int   mi[K_TOP];
#pragma unroll
    for (int j = 0; j < K_TOP; ++j) { ms[j] = F_INF; mi[j] = 0; }

    for (int s = 0; s < SLICES; ++s) {
        const int task = group * SLICES + s;
        for (int k = 0; k < K_TOP; ++k) {
            float v = g_ps[(task * K_TOP + k) * 32 + lane];
            if (v >= ms[K_TOP - 1]) break;        // source sorted -> rest can't win
            topk_insert(ms, mi, v, g_pi[(task * K_TOP + k) * 32 + lane]);
        }
    }

    // shade: d = sqrt(|c|^2 + s), w = exp(-0.1 d) * sigmoid(op), normalized blend
    const float h = g_rays[r].w;
    float wsum = 0.f, a0 = 0.f, a1 = 0.f, a2 = 0.f;
#pragma unroll
    for (int k = 0; k < K_TOP; ++k) {
        int id   = mi[k];
        float d  = sqrtf(fmaxf(h + ms[k], 0.f));
        float wt = expf(-0.1f * d) * sigmoidf_(opac[id]);
        a0 += wt * sigmoidf_(fdc[3 * id + 0]);
        a1 += wt * sigmoidf_(fdc[3 * id + 1]);
        a2 += wt * sigmoidf_(fdc[3 * id + 2]);
        wsum += wt;
    }
    float inv = 1.f / (wsum + 1e-8f);
    out[3 * r + 0] = a0 * inv;
    out[3 * r + 1] = a1 * inv;
    out[3 * r + 2] = a2 * inv;
}

extern "C" void kernel_launch(void* const* d_in, const int* in_sizes, int n_in,
                              void* d_out, int out_size) {
    const float* ro  = (const float*)d_in[0];   // rays_o      [4096,3]
    const float* rd  = (const float*)d_in[1];   // rays_d      [4096,3]
    const float* xyz = (const float*)d_in[2];   // xyz         [100000,3]
    const float* fdc = (const float*)d_in[3];   // features_dc [100000,1,3]
    const float* op  = (const float*)d_in[4];   // opacity     [100000,1]
    float* out = (float*)d_out;                 // [4096,3] fp32

    prep_pairs_kernel<<<(N_PAD / 2 + 255) / 256, 256>>>(xyz);
    prep_rays_kernel<<<(N_RAYS + 255) / 256, 256>>>(ro, rd);
    scan_kernel<<<N_BLK, 256>>>();
    merge_kernel<<<(N_RAYS + 255) / 256, 256>>>(fdc, op, out);
}

// round 3
// speedup vs baseline: 1.0244x; 1.0244x over previous
#include <cuda_runtime.h>
#include <math.h>

// SimpleGaussianSplatting: B=4096 rays, N=100000 pts, top-K=10 nearest, weighted blend.
// R3: 2 kernels. (a) fused prep (point pairs + rays + counter reset).
//     (b) scan with IN-KERNEL merge: last task to finish a ray-group (atomic counter)
//     merges the group's 9x10 sorted candidate lists + shades, overlapped with other
//     warps still scanning. Kills the 67us latency-bound merge_kernel from R2.

#define N_PTS    100000
#define SLICES   9
#define L_PTS    11136                 // points per warp-slice, multiple of 64
#define N_PAD    (SLICES * L_PTS)      // 100224
#define N_RAYS   4096
#define K_TOP    10
#define N_GROUPS (N_RAYS / 32)         // 128
#define N_TASKS  (N_GROUPS * SLICES)   // 1152
#define N_BLK    (N_TASKS / 8)         // 144 blocks x 8 warps

#define F_INF __int_as_float(0x7f800000)

// Packed pair layout: g_pk[i] = (x0,x1,y0,y1), g_pk2[i] = (z0,z1,|p0|^2,|p1|^2)
__device__ float4 g_pk [N_PAD / 2];
__device__ float4 g_pk2[N_PAD / 2];
__device__ float4 g_rays[N_RAYS];      // (-2cx, -2cy, -2cz, |c|^2)
__device__ float  g_ps[N_TASKS * K_TOP * 32];
__device__ int    g_pi[N_TASKS * K_TOP * 32];
__device__ int    g_cnt[N_GROUPS];     // tasks completed per ray-group

#define FMA2(d, a, b, c) \
    asm("fma.rn.f32x2 %0, %1, %2, %3;" : "=l"(d) : "l"(a), "l"(b), "l"(c))
#define PACK2(d, f) \
    asm("mov.b64 %0, {%1, %1};" : "=l"(d) : "r"(__float_as_int(f)))
#define UNPK2(lo, hi, d) \
    asm("mov.b64 {%0, %1}, %2;" : "=f"(lo), "=f"(hi) : "l"(d))

// Fused prep: point pairs, ray constants, counter reset. One launch.
__global__ void prep_kernel(const float* __restrict__ xyz,
                            const float* __restrict__ ro,
                            const float* __restrict__ rd) {
    int i = blockIdx.x * blockDim.x + threadIdx.x;
    if (i < N_PAD / 2) {
        int p0 = 2 * i, p1 = 2 * i + 1;
        float x0 = 0.f, y0 = 0.f, z0 = 0.f, w0 = F_INF;
        float x1 = 0.f, y1 = 0.f, z1 = 0.f, w1 = F_INF;
        if (p0 < N_PTS) {
            x0 = xyz[3 * p0 + 0]; y0 = xyz[3 * p0 + 1]; z0 = xyz[3 * p0 + 2];
            w0 = x0 * x0 + y0 * y0 + z0 * z0;
        }
        if (p1 < N_PTS) {
            x1 = xyz[3 * p1 + 0]; y1 = xyz[3 * p1 + 1]; z1 = xyz[3 * p1 + 2];
            w1 = x1 * x1 + y1 * y1 + z1 * z1;
        }
        g_pk [i] = make_float4(x0, x1, y0, y1);
        g_pk2[i] = make_float4(z0, z1, w0, w1);
    }
    if (i < N_RAYS) {
        float cx = ro[3 * i + 0] + 3.f * rd[3 * i + 0];
        float cy = ro[3 * i + 1] + 3.f * rd[3 * i + 1];
        float cz = ro[3 * i + 2] + 3.f * rd[3 * i + 2];
        g_rays[i] = make_float4(-2.f * cx, -2.f * cy, -2.f * cz,
                                cx * cx + cy * cy + cz * cz);
    }
    if (i < N_GROUPS) g_cnt[i] = 0;    // deterministic reset per replay
}

__device__ __forceinline__ float sigmoidf_(float x) {
    return 1.f / (1.f + expf(-x));
}

// Branchless sorted insert (ascending); fully unrolled -> stays in registers.
__device__ __forceinline__ void topk_insert(float (&sa)[K_TOP], int (&ia)[K_TOP],
                                            float s, int vi) {
    bool cc[K_TOP];
#pragma unroll
    for (int j = 0; j < K_TOP; ++j) cc[j] = s < sa[j];
#pragma unroll
    for (int j = K_TOP - 1; j >= 1; --j) {
        sa[j] = cc[j - 1] ? sa[j - 1] : (cc[j] ? s  : sa[j]);
        ia[j] = cc[j - 1] ? ia[j - 1] : (cc[j] ? vi : ia[j]);
    }
    sa[0] = cc[0] ? s  : sa[0];
    ia[0] = cc[0] ? vi : ia[0];
}

__global__ __launch_bounds__(256, 1)
void scan_kernel(const float* __restrict__ fdc,
                 const float* __restrict__ opac,
                 float* __restrict__ out) {
    __shared__ ulonglong2 sA[8][32];   // (x0x1, y0y1) bit-packed
    __shared__ ulonglong2 sB[8][32];   // (z0z1, w0w1)

    const int lane = threadIdx.x & 31;
    const int w    = threadIdx.x >> 5;
    const int task  = blockIdx.x * 8 + w;         // 0..1151
    const int group = task / SLICES;              // 0..127
    const int slice = task - group * SLICES;      // 0..8
    const int ray   = group * 32 + lane;

    const float4 rc = g_rays[ray];
    unsigned long long rcx2, rcy2, rcz2;
    PACK2(rcx2, rc.x);
    PACK2(rcy2, rc.y);
    PACK2(rcz2, rc.z);

    float sa[K_TOP];
    int   ia[K_TOP];
#pragma unroll
    for (int j = 0; j < K_TOP; ++j) { sa[j] = F_INF; ia[j] = 0; }

    const ulonglong2* __restrict__ gA = reinterpret_cast<const ulonglong2*>(g_pk);
    const ulonglong2* __restrict__ gB = reinterpret_cast<const ulonglong2*>(g_pk2);
    const int pbase = slice * (L_PTS / 2);        // pair index base (5568/slice)

    ulonglong2 nA = gA[pbase + lane];             // prefetch chunk 0
    ulonglong2 nB = gB[pbase + lane];

    for (int c = 0; c < L_PTS / 2; c += 32) {
        __syncwarp();
        sA[w][lane] = nA;
        sB[w][lane] = nB;
        __syncwarp();
        if (c + 32 < L_PTS / 2) {
            nA = gA[pbase + c + 32 + lane];       // hide L2 latency
            nB = gB[pbase + c + 32 + lane];
        }

#pragma unroll 4
        for (int k = 0; k < 32; ++k) {
            ulonglong2 A = sA[w][k];              // broadcast LDS.128
            ulonglong2 B = sB[w][k];
            unsigned long long t;
            FMA2(t, rcz2, B.x, B.y);              // z*rcz + |p|^2   (2 pts)
            FMA2(t, rcy2, A.y, t);                // + y*rcy
            FMA2(t, rcx2, A.x, t);                // + x*rcx
            float s0, s1;
            UNPK2(s0, s1, t);                     // free: register-pair split
            const int pi = (pbase + c + k) * 2;
            // per-point warp-uniform guards (per-pair guard doubles body rate)
            if (__any_sync(0xffffffffu, s0 < sa[K_TOP - 1]))
                topk_insert(sa, ia, s0, pi);
            if (__any_sync(0xffffffffu, s1 < sa[K_TOP - 1]))
                topk_insert(sa, ia, s1, pi + 1);
        }
    }

    // publish sorted per-task candidates, coalesced by lane
#pragma unroll
    for (int j = 0; j < K_TOP; ++j) {
        g_ps[(task * K_TOP + j) * 32 + lane] = sa[j];
        g_pi[(task * K_TOP + j) * 32 + lane] = ia[j];
    }

    // ---- in-kernel merge: last task of this ray-group merges + shades ----
    __threadfence();                              // publish g_ps/g_pi (release)
    int done = 0;
    if (lane == 0) done = atomicAdd(&g_cnt[group], 1);
    done = __shfl_sync(0xffffffffu, done, 0);
    if (done != SLICES - 1) return;               // not the last -> exit
    __threadfence();                              // acquire other tasks' writes

    // lane = ray within group; merge 9 sorted 10-lists (latency hidden by
    // co-resident warps still scanning)
    float ms[K_TOP];
    int   mi[K_TOP];
#pragma unroll
    for (int j = 0; j < K_TOP; ++j) { ms[j] = F_INF; mi[j] = 0; }

    for (int s = 0; s < SLICES; ++s) {
        const int t0 = (group * SLICES + s) * K_TOP;
        for (int k = 0; k < K_TOP; ++k) {
            float v = g_ps[(t0 + k) * 32 + lane];
            if (v >= ms[K_TOP - 1]) break;        // source sorted -> rest can't win
            topk_insert(ms, mi, v, g_pi[(t0 + k) * 32 + lane]);
        }
    }

    // shade: d = sqrt(|c|^2 + s), wt = exp(-0.1 d) * sigmoid(op), normalized blend
    const float h = rc.w;
    float wsum = 0.f, a0 = 0.f, a1 = 0.f, a2 = 0.f;
#pragma unroll
    for (int k = 0; k < K_TOP; ++k) {
        int id   = mi[k];
        float d  = sqrtf(fmaxf(h + ms[k], 0.f));
        float wt = expf(-0.1f * d) * sigmoidf_(opac[id]);
        a0 += wt * sigmoidf_(fdc[3 * id + 0]);
        a1 += wt * sigmoidf_(fdc[3 * id + 1]);
        a2 += wt * sigmoidf_(fdc[3 * id + 2]);
        wsum += wt;
    }
    float inv = 1.f / (wsum + 1e-8f);
    out[3 * ray + 0] = a0 * inv;
    out[3 * ray + 1] = a1 * inv;
    out[3 * ray + 2] = a2 * inv;
}

extern "C" void kernel_launch(void* const* d_in, const int* in_sizes, int n_in,
                              void* d_out, int out_size) {
    const float* ro  = (const float*)d_in[0];   // rays_o      [4096,3]
    const float* rd  = (const float*)d_in[1];   // rays_d      [4096,3]
    const float* xyz = (const float*)d_in[2];   // xyz         [100000,3]
    const float* fdc = (const float*)d_in[3];   // features_dc [100000,1,3]
    const float* op  = (const float*)d_in[4];   // opacity     [100000,1]
    float* out = (float*)d_out;                 // [4096,3] fp32

    prep_kernel<<<(N_PAD / 2 + 255) / 256, 256>>>(xyz, ro, rd);
    scan_kernel<<<N_BLK, 256>>>(fdc, op, out);
}